// round 4
// baseline (speedup 1.0000x reference)
#include <cuda_runtime.h>

#define N_NODES 50000
#define N_EDGES 800000
#define TOT_E   (2 * N_EDGES)
#define D_FEAT  128
#define D_HID   128
#define N_CLS   64

// ---------------- scratch (device globals: no allocation allowed) ------------
__device__ int   g_deg[N_NODES];
__device__ float g_dinv[N_NODES];
__device__ int   g_rowptr[N_NODES + 1];
__device__ int   g_fill[N_NODES];
__device__ int   g_col[TOT_E];
__device__ float g_z[N_NODES * D_HID];   // x @ W0
__device__ float g_h[N_NODES * D_HID];   // relu(spmm(z))
__device__ float g_g[N_NODES * N_CLS];   // h @ W1

// ---------------- graph preprocessing ----------------------------------------
__global__ void init_kernel() {
    int i = blockIdx.x * blockDim.x + threadIdx.x;
    if (i < N_NODES) { g_deg[i] = 0; g_fill[i] = 0; }
}

__global__ void count_kernel(const int* __restrict__ ei) {
    int e = blockIdx.x * blockDim.x + threadIdx.x;
    if (e < N_EDGES) {
        atomicAdd(&g_deg[ei[e]], 1);
        atomicAdd(&g_deg[ei[N_EDGES + e]], 1);
    }
}

// single-block exclusive scan over degrees -> rowptr; also dinv = rsqrt(deg+1)
__global__ void scan_kernel() {
    __shared__ int sums[1024];
    const int CH = (N_NODES + 1023) / 1024;
    int t = threadIdx.x;
    int start = t * CH;
    int stop  = min(start + CH, N_NODES);
    int s = 0;
    for (int i = start; i < stop; i++) s += g_deg[i];
    sums[t] = s;
    __syncthreads();
    for (int off = 1; off < 1024; off <<= 1) {
        int v = (t >= off) ? sums[t - off] : 0;
        __syncthreads();
        sums[t] += v;
        __syncthreads();
    }
    int run = (t == 0) ? 0 : sums[t - 1];
    for (int i = start; i < stop; i++) {
        g_rowptr[i] = run;
        int d = g_deg[i];
        run += d;
        g_dinv[i] = rsqrtf((float)(d + 1));   // +1 self loop
    }
    if (t == 1023) g_rowptr[N_NODES] = sums[1023];
}

__global__ void scatter_kernel(const int* __restrict__ ei) {
    int e = blockIdx.x * blockDim.x + threadIdx.x;
    if (e < N_EDGES) {
        int s = ei[e], d = ei[N_EDGES + e];
        int p = atomicAdd(&g_fill[s], 1);
        g_col[g_rowptr[s] + p] = d;
        int q = atomicAdd(&g_fill[d], 1);
        g_col[g_rowptr[d] + q] = s;
    }
}

// ---------------- SGEMM: Z[M,NCOLS] = X[M,128] * W[128,NCOLS] ----------------
// BM=64, BK=32, 256 threads, per-thread 4 rows x TN cols.
// Xs stored transposed [k][row] with stride 65 -> conflict-free STS & LDS.
template <int NCOLS, int TN>
__global__ __launch_bounds__(256) void gemm_kernel(const float* __restrict__ X,
                                                   const float* __restrict__ W,
                                                   float* __restrict__ Z) {
    __shared__ float Xs[32 * 65];
    __shared__ float Ws[32 * NCOLS];
    const int tid  = threadIdx.x;
    const int row0 = blockIdx.x * 64;
    const int tx = tid & 15;
    const int ty = tid >> 4;
    const int cr = ty * 4;
    const int cc = tx * TN;

    float acc[4][TN];
#pragma unroll
    for (int i = 0; i < 4; i++)
#pragma unroll
        for (int j = 0; j < TN; j++) acc[i][j] = 0.f;

    for (int kk = 0; kk < 128; kk += 32) {
        for (int i = tid; i < 64 * 32; i += 256) {
            int r = i >> 5, k = i & 31;
            int gr = row0 + r;
            Xs[k * 65 + r] = (gr < N_NODES) ? X[gr * 128 + kk + k] : 0.f;
        }
        for (int i = tid; i < 32 * NCOLS; i += 256) {
            int k = i / NCOLS, c = i % NCOLS;
            Ws[k * NCOLS + c] = W[(kk + k) * NCOLS + c];
        }
        __syncthreads();
#pragma unroll 8
        for (int k = 0; k < 32; k++) {
            float a0 = Xs[k * 65 + cr + 0];
            float a1 = Xs[k * 65 + cr + 1];
            float a2 = Xs[k * 65 + cr + 2];
            float a3 = Xs[k * 65 + cr + 3];
            float b[TN];
#pragma unroll
            for (int j = 0; j < TN; j++) b[j] = Ws[k * NCOLS + cc + j];
#pragma unroll
            for (int j = 0; j < TN; j++) {
                acc[0][j] += a0 * b[j];
                acc[1][j] += a1 * b[j];
                acc[2][j] += a2 * b[j];
                acc[3][j] += a3 * b[j];
            }
        }
        __syncthreads();
    }
#pragma unroll
    for (int i = 0; i < 4; i++) {
        int gr = row0 + cr + i;
        if (gr < N_NODES) {
#pragma unroll
            for (int j = 0; j < TN; j += 4) {
                float4 v = make_float4(acc[i][j], acc[i][j + 1],
                                       acc[i][j + 2], acc[i][j + 3]);
                *(float4*)&Z[gr * NCOLS + cc + j] = v;
            }
        }
    }
}

// ---------------- SPMM (gather, 1 warp per row) -------------------------------
// h[r] = relu( dinv[r] * ( sum_{c in adj(r)} dinv[c]*z[c] + dinv[r]*z[r] ) )
__global__ __launch_bounds__(256) void spmm_relu_128() {
    int warp = (blockIdx.x * 256 + threadIdx.x) >> 5;
    int lane = threadIdx.x & 31;
    if (warp >= N_NODES) return;
    int r   = warp;
    int beg = g_rowptr[r], end = g_rowptr[r + 1];
    float dr = g_dinv[r];
    const float4* z4 = (const float4*)g_z;
    float4 zr = z4[r * 32 + lane];
    float4 acc = make_float4(dr * zr.x, dr * zr.y, dr * zr.z, dr * zr.w);
    for (int j = beg; j < end; j += 32) {
        int idx = j + lane;
        int c = 0; float wv = 0.f;
        if (idx < end) { c = g_col[idx]; wv = g_dinv[c]; }
        int cnt = min(32, end - j);
        for (int t = 0; t < cnt; t++) {
            int   cidx = __shfl_sync(0xffffffffu, c,  t);
            float w    = __shfl_sync(0xffffffffu, wv, t);
            float4 zc = z4[cidx * 32 + lane];
            acc.x += w * zc.x; acc.y += w * zc.y;
            acc.z += w * zc.z; acc.w += w * zc.w;
        }
    }
    acc.x = fmaxf(acc.x * dr, 0.f);
    acc.y = fmaxf(acc.y * dr, 0.f);
    acc.z = fmaxf(acc.z * dr, 0.f);
    acc.w = fmaxf(acc.w * dr, 0.f);
    ((float4*)g_h)[r * 32 + lane] = acc;
}

// out[r] = dinv[r] * ( sum dinv[c]*g[c] + dinv[r]*g[r] ),  F = 64 (float2/lane)
__global__ __launch_bounds__(256) void spmm_64(float* __restrict__ out) {
    int warp = (blockIdx.x * 256 + threadIdx.x) >> 5;
    int lane = threadIdx.x & 31;
    if (warp >= N_NODES) return;
    int r   = warp;
    int beg = g_rowptr[r], end = g_rowptr[r + 1];
    float dr = g_dinv[r];
    const float2* g2 = (const float2*)g_g;
    float2 zr = g2[r * 32 + lane];
    float2 acc = make_float2(dr * zr.x, dr * zr.y);
    for (int j = beg; j < end; j += 32) {
        int idx = j + lane;
        int c = 0; float wv = 0.f;
        if (idx < end) { c = g_col[idx]; wv = g_dinv[c]; }
        int cnt = min(32, end - j);
        for (int t = 0; t < cnt; t++) {
            int   cidx = __shfl_sync(0xffffffffu, c,  t);
            float w    = __shfl_sync(0xffffffffu, wv, t);
            float2 zc = g2[cidx * 32 + lane];
            acc.x += w * zc.x; acc.y += w * zc.y;
        }
    }
    acc.x *= dr; acc.y *= dr;
    ((float2*)out)[r * 32 + lane] = acc;
}

// ---------------- launch ------------------------------------------------------
extern "C" void kernel_launch(void* const* d_in, const int* in_sizes, int n_in,
                              void* d_out, int out_size) {
    const float* x  = (const float*)d_in[0];
    const float* W0 = (const float*)d_in[1];
    const float* W1 = (const float*)d_in[2];
    const int*   ei = (const int*)d_in[3];
    float* out = (float*)d_out;

    void *pz = nullptr, *ph = nullptr, *pg = nullptr;
    cudaGetSymbolAddress(&pz, g_z);
    cudaGetSymbolAddress(&ph, g_h);
    cudaGetSymbolAddress(&pg, g_g);

    init_kernel   <<<(N_NODES + 255) / 256, 256>>>();
    count_kernel  <<<(N_EDGES + 255) / 256, 256>>>(ei);
    scan_kernel   <<<1, 1024>>>();
    scatter_kernel<<<(N_EDGES + 255) / 256, 256>>>(ei);

    gemm_kernel<128, 8><<<(N_NODES + 63) / 64, 256>>>(x, W0, (float*)pz);
    spmm_relu_128      <<<(N_NODES * 32 + 255) / 256, 256>>>();
    gemm_kernel<64, 4> <<<(N_NODES + 63) / 64, 256>>>((const float*)ph, W1, (float*)pg);
    spmm_64            <<<(N_NODES * 32 + 255) / 256, 256>>>(out);
}

// round 5
// speedup vs baseline: 1.1173x; 1.1173x over previous
#include <cuda_runtime.h>
#include <cuda_fp16.h>

#define N_NODES 50000
#define N_EDGES 800000
#define TOT_E   (2 * N_EDGES)
#define D_FEAT  128
#define D_HID   128
#define N_CLS   64

// ---------------- scratch (device globals: no allocation allowed) ------------
__device__ int    g_deg[N_NODES];
__device__ float  g_dinv[N_NODES];
__device__ int    g_rowptr[N_NODES + 1];
__device__ int    g_fill[N_NODES];
__device__ int    g_col[TOT_E];
__device__ __half g_zh[N_NODES * D_HID];   // dinv[r] * (x @ W0)[r]   (fp16)
__device__ float  g_h [N_NODES * D_HID];   // relu(spmm1)             (fp32)
__device__ __half g_gh[N_NODES * N_CLS];   // dinv[r] * (h @ W1)[r]   (fp16)

// ---------------- graph preprocessing ----------------------------------------
__global__ void init_kernel() {
    int i = blockIdx.x * blockDim.x + threadIdx.x;
    if (i < N_NODES) { g_deg[i] = 0; g_fill[i] = 0; }
}

__global__ void count_kernel(const int* __restrict__ ei) {
    int e = blockIdx.x * blockDim.x + threadIdx.x;
    if (e < N_EDGES) {
        atomicAdd(&g_deg[ei[e]], 1);
        atomicAdd(&g_deg[ei[N_EDGES + e]], 1);
    }
}

// single-block exclusive scan over degrees -> rowptr; also dinv = rsqrt(deg+1)
__global__ void scan_kernel() {
    __shared__ int sums[1024];
    const int CH = (N_NODES + 1023) / 1024;
    int t = threadIdx.x;
    int start = t * CH;
    int stop  = min(start + CH, N_NODES);
    int s = 0;
    for (int i = start; i < stop; i++) s += g_deg[i];
    sums[t] = s;
    __syncthreads();
    for (int off = 1; off < 1024; off <<= 1) {
        int v = (t >= off) ? sums[t - off] : 0;
        __syncthreads();
        sums[t] += v;
        __syncthreads();
    }
    int run = (t == 0) ? 0 : sums[t - 1];
    for (int i = start; i < stop; i++) {
        g_rowptr[i] = run;
        int d = g_deg[i];
        run += d;
        g_dinv[i] = rsqrtf((float)(d + 1));   // +1 self loop
    }
    if (t == 1023) g_rowptr[N_NODES] = sums[1023];
}

__global__ void scatter_kernel(const int* __restrict__ ei) {
    int e = blockIdx.x * blockDim.x + threadIdx.x;
    if (e < N_EDGES) {
        int s = ei[e], d = ei[N_EDGES + e];
        int p = atomicAdd(&g_fill[s], 1);
        g_col[g_rowptr[s] + p] = d;
        int q = atomicAdd(&g_fill[d], 1);
        g_col[g_rowptr[d] + q] = s;
    }
}

// ---------------- SGEMM: Zh[M,NCOLS] = fp16( dinv[r] * (X[M,128] @ W[128,NCOLS]) )
// BM=64, BK=32, 256 threads, per-thread 4 rows x TN cols.
// Xs stored transposed [k][row] with stride 65 -> conflict-free STS & LDS.
template <int NCOLS, int TN>
__global__ __launch_bounds__(256) void gemm_kernel(const float* __restrict__ X,
                                                   const float* __restrict__ W,
                                                   __half* __restrict__ Z) {
    __shared__ float Xs[32 * 65];
    __shared__ float Ws[32 * NCOLS];
    const int tid  = threadIdx.x;
    const int row0 = blockIdx.x * 64;
    const int tx = tid & 15;
    const int ty = tid >> 4;
    const int cr = ty * 4;
    const int cc = tx * TN;

    float acc[4][TN];
#pragma unroll
    for (int i = 0; i < 4; i++)
#pragma unroll
        for (int j = 0; j < TN; j++) acc[i][j] = 0.f;

    for (int kk = 0; kk < 128; kk += 32) {
        for (int i = tid; i < 64 * 32; i += 256) {
            int r = i >> 5, k = i & 31;
            int gr = row0 + r;
            Xs[k * 65 + r] = (gr < N_NODES) ? X[gr * 128 + kk + k] : 0.f;
        }
        for (int i = tid; i < 32 * NCOLS; i += 256) {
            int k = i / NCOLS, c = i % NCOLS;
            Ws[k * NCOLS + c] = W[(kk + k) * NCOLS + c];
        }
        __syncthreads();
#pragma unroll 8
        for (int k = 0; k < 32; k++) {
            float a0 = Xs[k * 65 + cr + 0];
            float a1 = Xs[k * 65 + cr + 1];
            float a2 = Xs[k * 65 + cr + 2];
            float a3 = Xs[k * 65 + cr + 3];
            float b[TN];
#pragma unroll
            for (int j = 0; j < TN; j++) b[j] = Ws[k * NCOLS + cc + j];
#pragma unroll
            for (int j = 0; j < TN; j++) {
                acc[0][j] += a0 * b[j];
                acc[1][j] += a1 * b[j];
                acc[2][j] += a2 * b[j];
                acc[3][j] += a3 * b[j];
            }
        }
        __syncthreads();
    }
#pragma unroll
    for (int i = 0; i < 4; i++) {
        int gr = row0 + cr + i;
        if (gr < N_NODES) {
            float d = g_dinv[gr];
#pragma unroll
            for (int j = 0; j < TN; j += 2) {
                __half2 h2 = __float22half2_rn(
                    make_float2(acc[i][j] * d, acc[i][j + 1] * d));
                *(__half2*)&Z[gr * NCOLS + cc + j] = h2;
            }
        }
    }
}

// ---------------- SPMM layer 1 (gather fp16, fp32 accum, 1 warp per row) ------
// h[r] = relu( dr * ( sum_{c in adj(r)} zs[c] + zs[r] ) ),  zs = dinv.*z
__global__ __launch_bounds__(256) void spmm_relu_128() {
    int warp = (blockIdx.x * 256 + threadIdx.x) >> 5;
    int lane = threadIdx.x & 31;
    if (warp >= N_NODES) return;
    int r   = warp;
    int beg = g_rowptr[r], end = g_rowptr[r + 1];
    float dr = g_dinv[r];
    const __half2* zh = (const __half2*)g_zh;   // 64 half2 per row

    // self term
    __half2 s0 = zh[r * 64 + lane * 2];
    __half2 s1 = zh[r * 64 + lane * 2 + 1];
    float2 f0 = __half22float2(s0), f1 = __half22float2(s1);
    float ax = f0.x, ay = f0.y, az = f1.x, aw = f1.y;

    for (int j = beg; j < end; j += 32) {
        int idx = j + lane;
        int c = (idx < end) ? g_col[idx] : 0;
        int cnt = min(32, end - j);
        if (cnt == 32) {
#pragma unroll 4
            for (int t = 0; t < 32; t++) {
                int cidx = __shfl_sync(0xffffffffu, c, t);
                __half2 v0 = zh[cidx * 64 + lane * 2];
                __half2 v1 = zh[cidx * 64 + lane * 2 + 1];
                float2 g0 = __half22float2(v0), g1 = __half22float2(v1);
                ax += g0.x; ay += g0.y; az += g1.x; aw += g1.y;
            }
        } else {
            for (int t = 0; t < cnt; t++) {
                int cidx = __shfl_sync(0xffffffffu, c, t);
                __half2 v0 = zh[cidx * 64 + lane * 2];
                __half2 v1 = zh[cidx * 64 + lane * 2 + 1];
                float2 g0 = __half22float2(v0), g1 = __half22float2(v1);
                ax += g0.x; ay += g0.y; az += g1.x; aw += g1.y;
            }
        }
    }
    float4 o;
    o.x = fmaxf(ax * dr, 0.f);
    o.y = fmaxf(ay * dr, 0.f);
    o.z = fmaxf(az * dr, 0.f);
    o.w = fmaxf(aw * dr, 0.f);
    ((float4*)g_h)[r * 32 + lane] = o;
}

// ---------------- SPMM layer 2 (64 feats, fp16 gather, fp32 out) --------------
// out[r] = dr * ( sum gs[c] + gs[r] ),  gs = dinv.*g
__global__ __launch_bounds__(256) void spmm_64(float* __restrict__ out) {
    int warp = (blockIdx.x * 256 + threadIdx.x) >> 5;
    int lane = threadIdx.x & 31;
    if (warp >= N_NODES) return;
    int r   = warp;
    int beg = g_rowptr[r], end = g_rowptr[r + 1];
    float dr = g_dinv[r];
    const __half2* gh = (const __half2*)g_gh;   // 32 half2 per row

    __half2 s0 = gh[r * 32 + lane];
    float2 f0 = __half22float2(s0);
    float ax = f0.x, ay = f0.y;

    for (int j = beg; j < end; j += 32) {
        int idx = j + lane;
        int c = (idx < end) ? g_col[idx] : 0;
        int cnt = min(32, end - j);
        if (cnt == 32) {
#pragma unroll 4
            for (int t = 0; t < 32; t++) {
                int cidx = __shfl_sync(0xffffffffu, c, t);
                float2 g0 = __half22float2(gh[cidx * 32 + lane]);
                ax += g0.x; ay += g0.y;
            }
        } else {
            for (int t = 0; t < cnt; t++) {
                int cidx = __shfl_sync(0xffffffffu, c, t);
                float2 g0 = __half22float2(gh[cidx * 32 + lane]);
                ax += g0.x; ay += g0.y;
            }
        }
    }
    ((float2*)out)[r * 32 + lane] = make_float2(ax * dr, ay * dr);
}

// ---------------- launch ------------------------------------------------------
extern "C" void kernel_launch(void* const* d_in, const int* in_sizes, int n_in,
                              void* d_out, int out_size) {
    const float* x  = (const float*)d_in[0];
    const float* W0 = (const float*)d_in[1];
    const float* W1 = (const float*)d_in[2];
    const int*   ei = (const int*)d_in[3];
    float* out = (float*)d_out;

    void *pz = nullptr, *ph = nullptr, *pg = nullptr;
    cudaGetSymbolAddress(&pz, g_zh);
    cudaGetSymbolAddress(&ph, g_h);
    cudaGetSymbolAddress(&pg, g_gh);

    init_kernel   <<<(N_NODES + 255) / 256, 256>>>();
    count_kernel  <<<(N_EDGES + 255) / 256, 256>>>(ei);
    scan_kernel   <<<1, 1024>>>();
    scatter_kernel<<<(N_EDGES + 255) / 256, 256>>>(ei);

    gemm_kernel<128, 8><<<(N_NODES + 63) / 64, 256>>>(x, W0, (__half*)pz);
    spmm_relu_128      <<<(N_NODES * 32 + 255) / 256, 256>>>();
    gemm_kernel<64, 4> <<<(N_NODES + 63) / 64, 256>>>((const float*)ph, W1, (__half*)pg);
    spmm_64            <<<(N_NODES * 32 + 255) / 256, 256>>>(out);
}

// round 6
// speedup vs baseline: 1.4504x; 1.2982x over previous
#include <cuda_runtime.h>
#include <cuda_fp16.h>
#include <mma.h>

using namespace nvcuda;

#define N_NODES 50000
#define N_EDGES 800000
#define TOT_E   (2 * N_EDGES)
#define D_FEAT  128
#define D_HID   128
#define N_CLS   64

// ---------------- scratch (device globals: no allocation allowed) ------------
__device__ int    g_deg[N_NODES];
__device__ float  g_dinv[N_NODES];
__device__ int    g_rowptr[N_NODES + 1];
__device__ int    g_fill[N_NODES];
__device__ int    g_col[TOT_E];
__device__ __half g_xh [N_NODES * D_FEAT];  // dinv[r] * x[r]            (fp16)
__device__ __half g_w0h[D_FEAT * D_HID];    // W0                        (fp16)
__device__ __half g_w1h[D_HID * N_CLS];     // W1                        (fp16)
__device__ __half g_zh [N_NODES * D_HID];   // dinv[r]*(x@W0)[r] = zs    (fp16)
__device__ __half g_hh [N_NODES * D_HID];   // dinv[r]*relu(spmm1)[r]    (fp16)
__device__ __half g_gh [N_NODES * N_CLS];   // dinv[r]*(h@W1)[r] = gs    (fp16)

// ---------------- graph preprocessing ----------------------------------------
__global__ void init_kernel() {
    int i = blockIdx.x * blockDim.x + threadIdx.x;
    if (i < N_NODES) { g_deg[i] = 0; g_fill[i] = 0; }
}

__global__ void count_kernel(const int* __restrict__ ei) {
    int e = blockIdx.x * blockDim.x + threadIdx.x;
    if (e < N_EDGES) {
        atomicAdd(&g_deg[ei[e]], 1);
        atomicAdd(&g_deg[ei[N_EDGES + e]], 1);
    }
}

// single-block exclusive scan over degrees -> rowptr; also dinv = rsqrt(deg+1)
__global__ void scan_kernel() {
    __shared__ int sums[1024];
    const int CH = (N_NODES + 1023) / 1024;
    int t = threadIdx.x;
    int start = t * CH;
    int stop  = min(start + CH, N_NODES);
    int s = 0;
    for (int i = start; i < stop; i++) s += g_deg[i];
    sums[t] = s;
    __syncthreads();
    for (int off = 1; off < 1024; off <<= 1) {
        int v = (t >= off) ? sums[t - off] : 0;
        __syncthreads();
        sums[t] += v;
        __syncthreads();
    }
    int run = (t == 0) ? 0 : sums[t - 1];
    for (int i = start; i < stop; i++) {
        g_rowptr[i] = run;
        int d = g_deg[i];
        run += d;
        g_dinv[i] = rsqrtf((float)(d + 1));   // +1 self loop
    }
    if (t == 1023) g_rowptr[N_NODES] = sums[1023];
}

__global__ void scatter_kernel(const int* __restrict__ ei) {
    int e = blockIdx.x * blockDim.x + threadIdx.x;
    if (e < N_EDGES) {
        int s = ei[e], d = ei[N_EDGES + e];
        int p = atomicAdd(&g_fill[s], 1);
        g_col[g_rowptr[s] + p] = d;
        int q = atomicAdd(&g_fill[d], 1);
        g_col[g_rowptr[d] + q] = s;
    }
}

// ---------------- fp16 conversions -------------------------------------------
// Xh[r] = fp16( dinv[r] * x[r] )   (float4 in, 2x half2 out per thread)
__global__ __launch_bounds__(256) void convert_x(const float* __restrict__ X) {
    int i = blockIdx.x * blockDim.x + threadIdx.x;   // over N*32 float4 chunks
    if (i >= N_NODES * 32) return;
    int r = i >> 5;
    float d = g_dinv[r];
    float4 v = ((const float4*)X)[i];
    __half2 h0 = __float22half2_rn(make_float2(v.x * d, v.y * d));
    __half2 h1 = __float22half2_rn(make_float2(v.z * d, v.w * d));
    uint2 p;
    p.x = *(unsigned*)&h0;
    p.y = *(unsigned*)&h1;
    ((uint2*)g_xh)[i] = p;
}

__global__ void convert_w(const float* __restrict__ W0,
                          const float* __restrict__ W1) {
    int i = blockIdx.x * blockDim.x + threadIdx.x;
    if (i < D_FEAT * D_HID) g_w0h[i] = __float2half(W0[i]);
    if (i < D_HID * N_CLS)  g_w1h[i] = __float2half(W1[i]);
}

// ---------------- tensor-core GEMM 1: zs = Xh(=dinv.*x) @ W0 -----------------
// BM=64, BN=128(full), BK=32. 8 warps in 2(M) x 4(N), each warp 32x32.
// Epilogue: fp32 frags -> per-warp smem staging -> fp16 store (no row scale:
// dinv is folded into A).
#define G1_SMEM 36864
__global__ __launch_bounds__(256) void gemm1_wmma() {
    __shared__ __align__(16) char smem[G1_SMEM];
    __half* As = (__half*)smem;                 // [64][40]
    __half* Bs = (__half*)(smem + 5120);        // [32][136]
    const int tid = threadIdx.x;
    const int wid = tid >> 5, lane = tid & 31;
    const int wm = wid >> 2, wn = wid & 3;
    const int row0 = blockIdx.x * 64;

    wmma::fragment<wmma::accumulator, 16, 16, 16, float> c[2][2];
#pragma unroll
    for (int i = 0; i < 2; i++)
#pragma unroll
        for (int j = 0; j < 2; j++) wmma::fill_fragment(c[i][j], 0.0f);

    for (int kk = 0; kk < 128; kk += 32) {
        // As: 64x32 halfs (as half2)
        for (int i = tid; i < 64 * 16; i += 256) {
            int r = i >> 4, k2 = i & 15;
            int gr = row0 + r;
            __half2 v = (gr < N_NODES)
                ? *(const __half2*)&g_xh[gr * 128 + kk + k2 * 2]
                : __half2(__float2half(0.f), __float2half(0.f));
            *(__half2*)&As[r * 40 + k2 * 2] = v;
        }
        // Bs: 32x128 halfs
        for (int i = tid; i < 32 * 64; i += 256) {
            int r = i >> 6, c2 = i & 63;
            *(__half2*)&Bs[r * 136 + c2 * 2] =
                *(const __half2*)&g_w0h[(kk + r) * 128 + c2 * 2];
        }
        __syncthreads();
#pragma unroll
        for (int k2 = 0; k2 < 32; k2 += 16) {
            wmma::fragment<wmma::matrix_a, 16, 16, 16, __half, wmma::row_major> a[2];
            wmma::fragment<wmma::matrix_b, 16, 16, 16, __half, wmma::row_major> b[2];
            wmma::load_matrix_sync(a[0], As + (wm * 32 +  0) * 40 + k2, 40);
            wmma::load_matrix_sync(a[1], As + (wm * 32 + 16) * 40 + k2, 40);
            wmma::load_matrix_sync(b[0], Bs + k2 * 136 + wn * 32 +  0, 136);
            wmma::load_matrix_sync(b[1], Bs + k2 * 136 + wn * 32 + 16, 136);
#pragma unroll
            for (int i = 0; i < 2; i++)
#pragma unroll
                for (int j = 0; j < 2; j++)
                    wmma::mma_sync(c[i][j], a[i], b[j], c[i][j]);
        }
        __syncthreads();
    }
    // epilogue: per-warp staging (32x36 fp32), overlays As/Bs (safe: synced)
    float* stg = (float*)smem + wid * (32 * 36);
#pragma unroll
    for (int i = 0; i < 2; i++)
#pragma unroll
        for (int j = 0; j < 2; j++)
            wmma::store_matrix_sync(stg + i * 16 * 36 + j * 16, c[i][j], 36,
                                    wmma::mem_row_major);
    __syncwarp();
    int hl = lane & 15, rs = lane >> 4;
    for (int r = rs; r < 32; r += 2) {
        int gr = row0 + wm * 32 + r;
        if (gr < N_NODES) {
            float f0 = stg[r * 36 + hl * 2];
            float f1 = stg[r * 36 + hl * 2 + 1];
            *(__half2*)&g_zh[gr * 128 + wn * 32 + hl * 2] =
                __float22half2_rn(make_float2(f0, f1));
        }
    }
}

// ---------------- tensor-core GEMM 2: gs = Hh(=dinv.*h) @ W1 -----------------
// BM=64, BN=64(full), BK=32. 4 warps in 2x2, each 32x32.
#define G2_SMEM 18432
__global__ __launch_bounds__(128) void gemm2_wmma() {
    __shared__ __align__(16) char smem[G2_SMEM];
    __half* As = (__half*)smem;                 // [64][40]
    __half* Bs = (__half*)(smem + 5120);        // [32][72]
    const int tid = threadIdx.x;
    const int wid = tid >> 5, lane = tid & 31;
    const int wm = wid >> 1, wn = wid & 1;
    const int row0 = blockIdx.x * 64;

    wmma::fragment<wmma::accumulator, 16, 16, 16, float> c[2][2];
#pragma unroll
    for (int i = 0; i < 2; i++)
#pragma unroll
        for (int j = 0; j < 2; j++) wmma::fill_fragment(c[i][j], 0.0f);

    for (int kk = 0; kk < 128; kk += 32) {
        for (int i = tid; i < 64 * 16; i += 128) {
            int r = i >> 4, k2 = i & 15;
            int gr = row0 + r;
            __half2 v = (gr < N_NODES)
                ? *(const __half2*)&g_hh[gr * 128 + kk + k2 * 2]
                : __half2(__float2half(0.f), __float2half(0.f));
            *(__half2*)&As[r * 40 + k2 * 2] = v;
        }
        for (int i = tid; i < 32 * 32; i += 128) {
            int r = i >> 5, c2 = i & 31;
            *(__half2*)&Bs[r * 72 + c2 * 2] =
                *(const __half2*)&g_w1h[(kk + r) * 64 + c2 * 2];
        }
        __syncthreads();
#pragma unroll
        for (int k2 = 0; k2 < 32; k2 += 16) {
            wmma::fragment<wmma::matrix_a, 16, 16, 16, __half, wmma::row_major> a[2];
            wmma::fragment<wmma::matrix_b, 16, 16, 16, __half, wmma::row_major> b[2];
            wmma::load_matrix_sync(a[0], As + (wm * 32 +  0) * 40 + k2, 40);
            wmma::load_matrix_sync(a[1], As + (wm * 32 + 16) * 40 + k2, 40);
            wmma::load_matrix_sync(b[0], Bs + k2 * 72 + wn * 32 +  0, 72);
            wmma::load_matrix_sync(b[1], Bs + k2 * 72 + wn * 32 + 16, 72);
#pragma unroll
            for (int i = 0; i < 2; i++)
#pragma unroll
                for (int j = 0; j < 2; j++)
                    wmma::mma_sync(c[i][j], a[i], b[j], c[i][j]);
        }
        __syncthreads();
    }
    float* stg = (float*)smem + wid * (32 * 36);
#pragma unroll
    for (int i = 0; i < 2; i++)
#pragma unroll
        for (int j = 0; j < 2; j++)
            wmma::store_matrix_sync(stg + i * 16 * 36 + j * 16, c[i][j], 36,
                                    wmma::mem_row_major);
    __syncwarp();
    int hl = lane & 15, rs = lane >> 4;
    for (int r = rs; r < 32; r += 2) {
        int gr = row0 + wm * 32 + r;
        if (gr < N_NODES) {
            float f0 = stg[r * 36 + hl * 2];
            float f1 = stg[r * 36 + hl * 2 + 1];
            *(__half2*)&g_gh[gr * 64 + wn * 32 + hl * 2] =
                __float22half2_rn(make_float2(f0, f1));
        }
    }
}

// ---------------- SPMM layer 1 (gather fp16 via LDG.64, fp32 accum) -----------
// S = sum_adj zs[c] + zs[r];  Hh[r] = fp16( relu(dr*dr*S) ) = dinv.*relu(spmm(z))
__global__ __launch_bounds__(256) void spmm_relu_128() {
    int warp = (blockIdx.x * 256 + threadIdx.x) >> 5;
    int lane = threadIdx.x & 31;
    if (warp >= N_NODES) return;
    int r   = warp;
    int beg = g_rowptr[r], end = g_rowptr[r + 1];
    float dr = g_dinv[r];
    const uint2* zp = (const uint2*)g_zh;   // 32 uint2 (4 halfs each) per row

    uint2 sp = zp[r * 32 + lane];
    __half2 s0 = *(__half2*)&sp.x, s1 = *(__half2*)&sp.y;
    float2 f0 = __half22float2(s0), f1 = __half22float2(s1);
    float ax = f0.x, ay = f0.y, az = f1.x, aw = f1.y;

    for (int j = beg; j < end; j += 32) {
        int idx = j + lane;
        int c = (idx < end) ? g_col[idx] : 0;
        int cnt = min(32, end - j);
        if (cnt == 32) {
#pragma unroll 4
            for (int t = 0; t < 32; t++) {
                int cidx = __shfl_sync(0xffffffffu, c, t);
                uint2 p = zp[cidx * 32 + lane];
                float2 g0 = __half22float2(*(__half2*)&p.x);
                float2 g1 = __half22float2(*(__half2*)&p.y);
                ax += g0.x; ay += g0.y; az += g1.x; aw += g1.y;
            }
        } else {
            for (int t = 0; t < cnt; t++) {
                int cidx = __shfl_sync(0xffffffffu, c, t);
                uint2 p = zp[cidx * 32 + lane];
                float2 g0 = __half22float2(*(__half2*)&p.x);
                float2 g1 = __half22float2(*(__half2*)&p.y);
                ax += g0.x; ay += g0.y; az += g1.x; aw += g1.y;
            }
        }
    }
    float m = dr * dr;
    __half2 o0 = __float22half2_rn(
        make_float2(fmaxf(ax * m, 0.f), fmaxf(ay * m, 0.f)));
    __half2 o1 = __float22half2_rn(
        make_float2(fmaxf(az * m, 0.f), fmaxf(aw * m, 0.f)));
    uint2 o;
    o.x = *(unsigned*)&o0;
    o.y = *(unsigned*)&o1;
    ((uint2*)g_hh)[r * 32 + lane] = o;
}

// ---------------- SPMM layer 2 (64 feats, fp16 gather, fp32 out) --------------
// out[r] = dr * ( sum_adj gs[c] + gs[r] )
__global__ __launch_bounds__(256) void spmm_64(float* __restrict__ out) {
    int warp = (blockIdx.x * 256 + threadIdx.x) >> 5;
    int lane = threadIdx.x & 31;
    if (warp >= N_NODES) return;
    int r   = warp;
    int beg = g_rowptr[r], end = g_rowptr[r + 1];
    float dr = g_dinv[r];
    const __half2* gh = (const __half2*)g_gh;   // 32 half2 per row

    float2 f0 = __half22float2(gh[r * 32 + lane]);
    float ax = f0.x, ay = f0.y;

    for (int j = beg; j < end; j += 32) {
        int idx = j + lane;
        int c = (idx < end) ? g_col[idx] : 0;
        int cnt = min(32, end - j);
        if (cnt == 32) {
#pragma unroll 4
            for (int t = 0; t < 32; t++) {
                int cidx = __shfl_sync(0xffffffffu, c, t);
                float2 g0 = __half22float2(gh[cidx * 32 + lane]);
                ax += g0.x; ay += g0.y;
            }
        } else {
            for (int t = 0; t < cnt; t++) {
                int cidx = __shfl_sync(0xffffffffu, c, t);
                float2 g0 = __half22float2(gh[cidx * 32 + lane]);
                ax += g0.x; ay += g0.y;
            }
        }
    }
    ((float2*)out)[r * 32 + lane] = make_float2(ax * dr, ay * dr);
}

// ---------------- launch ------------------------------------------------------
extern "C" void kernel_launch(void* const* d_in, const int* in_sizes, int n_in,
                              void* d_out, int out_size) {
    const float* x  = (const float*)d_in[0];
    const float* W0 = (const float*)d_in[1];
    const float* W1 = (const float*)d_in[2];
    const int*   ei = (const int*)d_in[3];
    float* out = (float*)d_out;

    init_kernel   <<<(N_NODES + 255) / 256, 256>>>();
    count_kernel  <<<(N_EDGES + 255) / 256, 256>>>(ei);
    scan_kernel   <<<1, 1024>>>();
    scatter_kernel<<<(N_EDGES + 255) / 256, 256>>>(ei);

    convert_w<<<(D_FEAT * D_HID + 255) / 256, 256>>>(W0, W1);
    convert_x<<<(N_NODES * 32 + 255) / 256, 256>>>(x);

    gemm1_wmma   <<<(N_NODES + 63) / 64, 256>>>();
    spmm_relu_128<<<(N_NODES * 32 + 255) / 256, 256>>>();
    gemm2_wmma   <<<(N_NODES + 63) / 64, 128>>>();
    spmm_64      <<<(N_NODES * 32 + 255) / 256, 256>>>(out);
}